// round 16
// baseline (speedup 1.0000x reference)
#include <cuda_runtime.h>
#include <cuda_fp16.h>
#include <cstdint>

#define NN   100000
#define FC   128
#define NE   1600000
#define NG   512
#define NOUT 10
#define NSCAN (NN + 1)
#define SCAN_BLK 1024
#define NBLK ((NSCAN + SCAN_BLK - 1) / SCAN_BLK)   // 98

// Scratch (device globals)
__device__ uint2    g_agg16[(size_t)NN * 32];   // fp16 aggregate  [NN][64 words]
__device__ uint2    g_f16a [(size_t)NN * 32];   // fp16 features ping
__device__ uint2    g_f16b [(size_t)NN * 32];   // fp16 features pong
__device__ uint32_t g_w16  [3 * 16384];         // pre-packed fp16 weights (3 layers)
__device__ int      g_rowptr[NSCAN];
__device__ int      g_cursor[NN];
__device__ int      g_esrc[NE];
__device__ int      g_part[NBLK];
__device__ int      g_is64;

// ---------------------------------------------------------------------------
// Index dtype detection (int32 vs int64 edge/batch buffers)
// ---------------------------------------------------------------------------
__global__ void detect_kernel(const long long* __restrict__ ei)
{
    __shared__ int ok;
    if (threadIdx.x == 0) ok = 1;
    __syncthreads();
    long long v = ei[threadIdx.x];           // 512 threads
    if (v < 0 || v >= NN) atomicAnd(&ok, 0);
    __syncthreads();
    if (threadIdx.x == 0) g_is64 = ok;
}

__device__ __forceinline__ long long load_idx(const void* base, int i, int is64)
{
    if (is64) return ((const long long*)base)[i];
    return (long long)((const int*)base)[i];
}

// ---------------------------------------------------------------------------
// CSR build: histogram -> scan -> fill
// ---------------------------------------------------------------------------
__global__ void hist_kernel(const void* __restrict__ ei, int* __restrict__ deg)
{
    int is64 = g_is64;
    for (int e = blockIdx.x * blockDim.x + threadIdx.x; e < NE;
         e += gridDim.x * blockDim.x) {
        int d = (int)load_idx(ei, e + NE, is64);
        atomicAdd(&deg[d + 1], 1);
    }
}

__global__ void scanA_kernel(int* __restrict__ deg, int* __restrict__ part)
{
    __shared__ int sm[SCAN_BLK];
    int tid = threadIdx.x;
    int i = blockIdx.x * SCAN_BLK + tid;
    int v = (i < NSCAN) ? deg[i] : 0;
    sm[tid] = v;
    __syncthreads();
#pragma unroll
    for (int off = 1; off < SCAN_BLK; off <<= 1) {
        int t = (tid >= off) ? sm[tid - off] : 0;
        __syncthreads();
        sm[tid] += t;
        __syncthreads();
    }
    if (i < NSCAN) deg[i] = sm[tid];
    if (tid == SCAN_BLK - 1) part[blockIdx.x] = sm[tid];
}

// scanC folds the cross-block partial prefix (98 partials) in-kernel.
__global__ void scanC_kernel(int* __restrict__ deg, const int* __restrict__ part,
                             int* __restrict__ cursor)
{
    __shared__ int soff;
    if (threadIdx.x == 0) soff = 0;
    __syncthreads();
    if (threadIdx.x < blockIdx.x)          // blockIdx.x <= 97 < blockDim
        atomicAdd(&soff, part[threadIdx.x]);
    __syncthreads();
    int i = blockIdx.x * SCAN_BLK + threadIdx.x;
    if (i < NSCAN) {
        int v = deg[i] + soff;
        deg[i] = v;
        if (i < NN) cursor[i] = v;
    }
}

__global__ void fill_kernel(const void* __restrict__ ei,
                            int* __restrict__ cursor, int* __restrict__ esrc)
{
    int is64 = g_is64;
    for (int e = blockIdx.x * blockDim.x + threadIdx.x; e < NE;
         e += gridDim.x * blockDim.x) {
        int s = (int)load_idx(ei, e, is64);
        int d = (int)load_idx(ei, e + NE, is64);
        int pos = atomicAdd(&cursor[d], 1);
        esrc[pos] = s;
    }
}

// ---------------------------------------------------------------------------
// fp32 -> fp16 convert (features)
// ---------------------------------------------------------------------------
__global__ void cvt16_kernel(const float4* __restrict__ src, uint2* __restrict__ dst)
{
    int i = blockIdx.x * blockDim.x + threadIdx.x;
    if (i >= NN * 32) return;
    float4 v = src[i];
    uint2 o;
    *(__half2*)&o.x = __floats2half2_rn(v.x, v.y);
    *(__half2*)&o.y = __floats2half2_rn(v.z, v.w);
    dst[i] = o;
}

// ---------------------------------------------------------------------------
// Weight pre-pack: dst[k2*128+n] = half2(W[2k2][n], W[2k2+1][n]) for the
// stacked [Wrel;Wroot] matrix. 16384 threads per layer.
// ---------------------------------------------------------------------------
__global__ void cvtW_kernel(const float* __restrict__ Wr,
                            const float* __restrict__ Ws,
                            uint32_t* __restrict__ dst)
{
    int i = blockIdx.x * blockDim.x + threadIdx.x;   // 0..16383
    int k2 = i >> 7;
    int n  = i & 127;
    const float* src = (k2 < 64) ? &Wr[(2 * k2) * FC + n]
                                 : &Ws[(2 * k2 - 128) * FC + n];
    __half2 h = __floats2half2_rn(src[0], src[FC]);
    dst[i] = *(uint32_t*)&h;
}

// ---------------------------------------------------------------------------
// Atomic-free fp16 gather (R10 scheme): agg16[n] = sum_{j in row n} xh[esrc[j]]
// ---------------------------------------------------------------------------
__global__ void gather_h_kernel(const uint2* __restrict__ xh,
                                const int* __restrict__ rowptr,
                                const int* __restrict__ esrc,
                                uint2* __restrict__ agg16)
{
    int n = blockIdx.x * 8 + (threadIdx.x >> 5);
    if (n >= NN) return;
    int c = threadIdx.x & 31;
    int lo = __ldg(&rowptr[n]);
    int hi = __ldg(&rowptr[n + 1]);
    float4 a0 = make_float4(0.f, 0.f, 0.f, 0.f);
    float4 a1 = make_float4(0.f, 0.f, 0.f, 0.f);
    int j = lo;
    for (; j + 1 < hi; j += 2) {
        int s0 = __ldg(&esrc[j]);
        int s1 = __ldg(&esrc[j + 1]);
        uint2 v0 = xh[(size_t)s0 * 32 + c];
        uint2 v1 = xh[(size_t)s1 * 32 + c];
        float2 p0 = __half22float2(*(__half2*)&v0.x);
        float2 p1 = __half22float2(*(__half2*)&v0.y);
        float2 q0 = __half22float2(*(__half2*)&v1.x);
        float2 q1 = __half22float2(*(__half2*)&v1.y);
        a0.x += p0.x; a0.y += p0.y; a0.z += p1.x; a0.w += p1.y;
        a1.x += q0.x; a1.y += q0.y; a1.z += q1.x; a1.w += q1.y;
    }
    if (j < hi) {
        int s0 = __ldg(&esrc[j]);
        uint2 v0 = xh[(size_t)s0 * 32 + c];
        float2 p0 = __half22float2(*(__half2*)&v0.x);
        float2 p1 = __half22float2(*(__half2*)&v0.y);
        a0.x += p0.x; a0.y += p0.y; a0.z += p1.x; a0.w += p1.y;
    }
    uint2 o;
    *(__half2*)&o.x = __floats2half2_rn(a0.x + a1.x, a0.y + a1.y);
    *(__half2*)&o.y = __floats2half2_rn(a0.z + a1.z, a0.w + a1.w);
    agg16[(size_t)n * 32 + c] = o;
}

// ---------------------------------------------------------------------------
// fp16 tensor-core GraphConv: out = (relu?)([A|X] @ [Wrel;Wroot] + b)
//   M=128/block, N=128, K=256, fp16 mma.m16n8k16, fp32 accumulate.
//   Pre-packed fp16 weights; double-buffered activation staging (1 sync/chunk).
//   2 blocks/SM (88KB smem). Emits fp16 output.
// ---------------------------------------------------------------------------
#define WS2 136
#define AS2 20
#define SWH_WORDS (128 * WS2)    // 17408
#define SAH_WORDS (128 * AS2)    //  2560 (per buffer)
#define GC_SMEM_BYTES ((SWH_WORDS + 2 * SAH_WORDS) * 4)   // 90112

__device__ __forceinline__ void mma_f16(float c[4],
                                        uint32_t a0, uint32_t a1,
                                        uint32_t a2, uint32_t a3,
                                        uint32_t b0, uint32_t b1)
{
    asm volatile("mma.sync.aligned.m16n8k16.row.col.f32.f16.f16.f32 "
                 "{%0,%1,%2,%3}, {%4,%5,%6,%7}, {%8,%9}, {%0,%1,%2,%3};"
                 : "+f"(c[0]), "+f"(c[1]), "+f"(c[2]), "+f"(c[3])
                 : "r"(a0), "r"(a1), "r"(a2), "r"(a3), "r"(b0), "r"(b1));
}

__global__ __launch_bounds__(256, 2) void gconv_h_kernel(
    const uint4* __restrict__ Ah, const uint4* __restrict__ Xh,
    const uint4* __restrict__ Wg,          // pre-packed fp16 weights (4096 uint4)
    const float* __restrict__ bias, uint32_t* __restrict__ out16, int do_relu)
{
    extern __shared__ uint32_t smw[];
    uint32_t* sW = smw;               // [k2 0..127][n 0..127] stride 136
    uint32_t* sA0 = smw + SWH_WORDS;  // activation buffers, stride 20
    uint32_t* sA1 = sA0 + SAH_WORDS;

    const int tid  = threadIdx.x;
    const int warp = tid >> 5;
    const int lane = tid & 31;
    const int rowBase = blockIdx.x * 128;

    const int wm = (warp & 3) * 32;   // warp rows [wm, wm+32)
    const int wn = (warp >> 2) * 64;  // warp cols [wn, wn+64)
    const int g8 = lane >> 2;
    const int ak = lane & 3;

    // ---- Stage pre-packed weights (pure copy, no convert) ----
    for (int i = tid; i < 4096; i += 256) {
        int k2 = i >> 5;
        int n4 = i & 31;
        uint4 v = Wg[i];
        uint32_t* d = &sW[k2 * WS2 + n4 * 4];
        d[0] = v.x; d[1] = v.y; d[2] = v.z; d[3] = v.w;
    }

    // ---- Stage chunk 0 (k [0,32) of agg) into buffer 0 ----
#pragma unroll
    for (int r = 0; r < 2; r++) {
        int idx = tid + r * 256;
        int row = idx >> 2;
        int q   = idx & 3;
        int grow = rowBase + row;
        uint4 v = make_uint4(0, 0, 0, 0);
        if (grow < NN) v = Ah[(size_t)grow * 16 + q];
        uint32_t* d = &sA0[row * AS2 + q * 4];
        d[0] = v.x; d[1] = v.y; d[2] = v.z; d[3] = v.w;
    }
    __syncthreads();

    float acc[2][8][4];
#pragma unroll
    for (int t = 0; t < 2; t++)
#pragma unroll
        for (int j = 0; j < 8; j++)
#pragma unroll
            for (int q = 0; q < 4; q++) acc[t][j][q] = 0.f;

    const int ar = (wm + g8) * AS2;

    uint4 pf[2];
#pragma unroll 1
    for (int c = 0; c < 8; c++) {
        uint32_t* sA = (c & 1) ? sA1 : sA0;
        if (c < 7) {
            const uint4* src = (c + 1 < 4) ? Ah : Xh;
            int cq = ((c + 1) & 3) * 4;
#pragma unroll
            for (int r = 0; r < 2; r++) {
                int idx = tid + r * 256;
                int row = idx >> 2;
                int q   = idx & 3;
                int grow = rowBase + row;
                pf[r] = (grow < NN) ? src[(size_t)grow * 16 + cq + q]
                                    : make_uint4(0, 0, 0, 0);
            }
        }

#pragma unroll
        for (int s = 0; s < 2; s++) {
            int kl = s * 8;
            uint32_t a00 = sA[ar + kl + ak];
            uint32_t a01 = sA[ar + 8 * AS2 + kl + ak];
            uint32_t a02 = sA[ar + kl + ak + 4];
            uint32_t a03 = sA[ar + 8 * AS2 + kl + ak + 4];
            uint32_t a10 = sA[ar + 16 * AS2 + kl + ak];
            uint32_t a11 = sA[ar + 24 * AS2 + kl + ak];
            uint32_t a12 = sA[ar + 16 * AS2 + kl + ak + 4];
            uint32_t a13 = sA[ar + 24 * AS2 + kl + ak + 4];
            int kg2 = c * 16 + kl;
            const uint32_t* bp = &sW[(kg2 + ak) * WS2 + wn + g8];
            uint32_t b0[8], b1[8];
#pragma unroll
            for (int j = 0; j < 8; j++) {
                b0[j] = bp[j * 8];
                b1[j] = bp[j * 8 + 4 * WS2];
            }
#pragma unroll
            for (int j = 0; j < 8; j++)
                mma_f16(acc[0][j], a00, a01, a02, a03, b0[j], b1[j]);
#pragma unroll
            for (int j = 0; j < 8; j++)
                mma_f16(acc[1][j], a10, a11, a12, a13, b0[j], b1[j]);
        }

        if (c < 7) {
            // Write chunk c+1 into the other buffer. Its previous readers
            // (chunk c-1) are fenced by the prior sync; one sync publishes it.
            uint32_t* sAn = (c & 1) ? sA0 : sA1;
#pragma unroll
            for (int r = 0; r < 2; r++) {
                int idx = tid + r * 256;
                int row = idx >> 2;
                int q   = idx & 3;
                uint32_t* d = &sAn[row * AS2 + q * 4];
                d[0] = pf[r].x; d[1] = pf[r].y; d[2] = pf[r].z; d[3] = pf[r].w;
            }
            __syncthreads();
        }
    }

    // ---- Epilogue: bias (+relu); fp16 stores ----
    const int coff = ak * 2;
    const int rbase = rowBase + wm + g8;
#pragma unroll
    for (int t = 0; t < 2; t++) {
        int ra = rbase + t * 16;
        int rb = ra + 8;
#pragma unroll
        for (int j = 0; j < 8; j++) {
            int col = wn + j * 8 + coff;
            float2 bb = *(const float2*)&bias[col];
            float2 o0, o1;
            o0.x = acc[t][j][0] + bb.x; o0.y = acc[t][j][1] + bb.y;
            o1.x = acc[t][j][2] + bb.x; o1.y = acc[t][j][3] + bb.y;
            if (do_relu) {
                o0.x = fmaxf(o0.x, 0.f); o0.y = fmaxf(o0.y, 0.f);
                o1.x = fmaxf(o1.x, 0.f); o1.y = fmaxf(o1.y, 0.f);
            }
            if (ra < NN)
                *(__half2*)&out16[(size_t)ra * 64 + (col >> 1)]
                    = __floats2half2_rn(o0.x, o0.y);
            if (rb < NN)
                *(__half2*)&out16[(size_t)rb * 64 + (col >> 1)]
                    = __floats2half2_rn(o1.x, o1.y);
        }
    }
}

// ---------------------------------------------------------------------------
// Fused mean-pool + classifier, fp16 input (batch sorted -> contiguous ranges)
// ---------------------------------------------------------------------------
__global__ void poolfinal_kernel(const __half* __restrict__ h16,
                                 const void* __restrict__ batch,
                                 const float* __restrict__ Wlin,
                                 const float* __restrict__ blin,
                                 float* __restrict__ out)
{
    __shared__ float sp[FC];
    __shared__ int bounds[2];
    int g = blockIdx.x;
    int t = threadIdx.x;
    int is64 = g_is64;

    if (t < 2) {
        long long target = g + t;
        int lo = 0, hi = NN;
        while (lo < hi) {
            int mid = (lo + hi) >> 1;
            if (load_idx(batch, mid, is64) < target) lo = mid + 1;
            else hi = mid;
        }
        bounds[t] = lo;
    }
    __syncthreads();
    int lo = bounds[0], hi = bounds[1];

    float s = 0.f;
    for (int n = lo; n < hi; n++)
        s += __half2float(h16[(size_t)n * FC + t]);
    float inv = 1.0f / fmaxf((float)(hi - lo), 1.0f);
    sp[t] = s * inv;
    __syncthreads();

    if (t < NOUT) {
        float acc = blin[t];
#pragma unroll 16
        for (int k = 0; k < FC; k++)
            acc += sp[k] * Wlin[k * NOUT + t];
        out[g * NOUT + t] = acc;
    }
}

// ---------------------------------------------------------------------------
extern "C" void kernel_launch(void* const* d_in, const int* in_sizes, int n_in,
                              void* d_out, int out_size)
{
    const float* x     = (const float*)d_in[0];
    const void*  ei    = d_in[1];
    const void*  batch = d_in[2];
    const float* W1r = (const float*)d_in[3];
    const float* b1  = (const float*)d_in[4];
    const float* W1s = (const float*)d_in[5];
    const float* W2r = (const float*)d_in[6];
    const float* b2  = (const float*)d_in[7];
    const float* W2s = (const float*)d_in[8];
    const float* W3r = (const float*)d_in[9];
    const float* b3  = (const float*)d_in[10];
    const float* W3s = (const float*)d_in[11];
    const float* Wl  = (const float*)d_in[12];
    const float* bl  = (const float*)d_in[13];
    float* out = (float*)d_out;

    cudaFuncSetAttribute(gconv_h_kernel,
                         cudaFuncAttributeMaxDynamicSharedMemorySize,
                         GC_SMEM_BYTES);

    uint2 *agg16, *f16a, *f16b;
    uint32_t *w16;
    int *rowptr, *cursor, *esrc, *part;
    cudaGetSymbolAddress((void**)&agg16,  g_agg16);
    cudaGetSymbolAddress((void**)&f16a,   g_f16a);
    cudaGetSymbolAddress((void**)&f16b,   g_f16b);
    cudaGetSymbolAddress((void**)&w16,    g_w16);
    cudaGetSymbolAddress((void**)&rowptr, g_rowptr);
    cudaGetSymbolAddress((void**)&cursor, g_cursor);
    cudaGetSymbolAddress((void**)&esrc,   g_esrc);
    cudaGetSymbolAddress((void**)&part,   g_part);

    const int nblocks8 = (NN + 7) / 8;
    const int gblocks  = (NN + 127) / 128;
    const int cblocks  = (NN * 32 + 255) / 256;

    detect_kernel<<<1, 512>>>((const long long*)ei);

    // ---- CSR build ----
    cudaMemsetAsync(rowptr, 0, NSCAN * sizeof(int));
    hist_kernel<<<2048, 256>>>(ei, rowptr);
    scanA_kernel<<<NBLK, SCAN_BLK>>>(rowptr, part);
    scanC_kernel<<<NBLK, SCAN_BLK>>>(rowptr, part, cursor);
    fill_kernel<<<2048, 256>>>(ei, cursor, esrc);

    // fp16 conversions (features + weights)
    cvt16_kernel<<<cblocks, 256>>>((const float4*)x, f16a);
    cvtW_kernel<<<64, 256>>>(W1r, W1s, w16);
    cvtW_kernel<<<64, 256>>>(W2r, W2s, w16 + 16384);
    cvtW_kernel<<<64, 256>>>(W3r, W3s, w16 + 32768);

    // Layer 1: f16a -> f16b
    gather_h_kernel<<<nblocks8, 256>>>(f16a, rowptr, esrc, agg16);
    gconv_h_kernel<<<gblocks, 256, GC_SMEM_BYTES>>>(
        (const uint4*)agg16, (const uint4*)f16a, (const uint4*)w16, b1,
        (uint32_t*)f16b, 1);
    // Layer 2: f16b -> f16a
    gather_h_kernel<<<nblocks8, 256>>>(f16b, rowptr, esrc, agg16);
    gconv_h_kernel<<<gblocks, 256, GC_SMEM_BYTES>>>(
        (const uint4*)agg16, (const uint4*)f16b, (const uint4*)(w16 + 16384), b2,
        (uint32_t*)f16a, 1);
    // Layer 3: f16a -> f16b (no relu)
    gather_h_kernel<<<nblocks8, 256>>>(f16a, rowptr, esrc, agg16);
    gconv_h_kernel<<<gblocks, 256, GC_SMEM_BYTES>>>(
        (const uint4*)agg16, (const uint4*)f16a, (const uint4*)(w16 + 32768), b3,
        (uint32_t*)f16b, 0);

    // Fused mean-pool + classifier (fp16 input)
    poolfinal_kernel<<<NG, FC>>>((const __half*)f16b, batch, Wl, bl, out);
}